// round 8
// baseline (speedup 1.0000x reference)
#include <cuda_runtime.h>

#define NN   20000
#define NE   640000
#define NEP  (NE + 4 * NN)    // padded edge capacity (pad to multiple of 4 per node)
#define F    128
#define NRBF 20
#define C3   384
#define ESTRIDE 32            // floats per edge record (128 B)
#define EBATCH 32
#define PI_OVER_5 0.6283185307179586f

typedef unsigned long long u64;

// ---------------- f32x2 packed-FMA helpers (sm_100+) -----------------------
__device__ __forceinline__ u64 pack2(float lo, float hi) {
    u64 r; asm("mov.b64 %0, {%1, %2};" : "=l"(r) : "f"(lo), "f"(hi)); return r;
}
__device__ __forceinline__ void unpack2(u64 v, float& lo, float& hi) {
    asm("mov.b64 {%0, %1}, %2;" : "=f"(lo), "=f"(hi) : "l"(v));
}
__device__ __forceinline__ u64 fma2(u64 a, u64 b, u64 c) {
    u64 d; asm("fma.rn.f32x2 %0, %1, %2, %3;" : "=l"(d) : "l"(a), "l"(b), "l"(c));
    return d;
}

// ---------------- scratch (__device__ globals; no allocation allowed) ------
__device__ int    g_is64;
__device__ int    g_cnt[NN];
__device__ int    g_cur[NN];
__device__ int    g_off[NN + 1];
__device__ float4 g_phiT[(size_t)NN * F];   // (phi0, phi1, phi2, vj0) per (node,f)
__device__ u64    g_vhi[(size_t)NN * F];    // (vj1, vj2) packed
__device__ float  g_edge[(size_t)NEP * ESTRIDE];

// ---------------- index helper: nbrs may be int64 or int32 ----------------
__device__ __forceinline__ int nb_get(const void* nbrs, long long k) {
    if (g_is64) return (int)((const long long*)nbrs)[k];
    return ((const int*)nbrs)[k];
}

__global__ void detect_kernel(const void* nbrs) {
    __shared__ int bad;
    if (threadIdx.x == 0) bad = 0;
    __syncthreads();
    const long long* p = (const long long*)nbrs;
    int mybad = 0;
    for (int e = threadIdx.x; e < 1024; e += 256) {
        long long a = p[2 * e], b = p[2 * e + 1];
        if (a < 0 || a >= NN || b < 0 || b >= NN) mybad = 1;
    }
    if (mybad) atomicOr(&bad, 1);
    __syncthreads();
    if (threadIdx.x == 0) g_is64 = !bad;
}

__global__ void zero_kernel() {
    int i = blockIdx.x * blockDim.x + threadIdx.x;
    if (i < NN) { g_cnt[i] = 0; g_cur[i] = 0; }
}

__global__ void hist_kernel(const void* nbrs) {
    int e = blockIdx.x * blockDim.x + threadIdx.x;
    if (e < NE) {
        int i = nb_get(nbrs, 2LL * e);
        atomicAdd(&g_cnt[i], 1);
    }
}

// Scan of PADDED counts (round each node's count up to a multiple of 4).
__global__ void scan_kernel() {
    __shared__ int sh[1024];
    __shared__ int carry;
    const int tid = threadIdx.x;
    if (tid == 0) carry = 0;
    __syncthreads();
    for (int base = 0; base < NN; base += 1024) {
        int i = base + tid;
        int v = (i < NN) ? ((g_cnt[i] + 3) & ~3) : 0;
        sh[tid] = v;
        __syncthreads();
        for (int s = 1; s < 1024; s <<= 1) {
            int t = (tid >= s) ? sh[tid - s] : 0;
            __syncthreads();
            sh[tid] += t;
            __syncthreads();
        }
        if (i < NN) g_off[i + 1] = carry + sh[tid];
        __syncthreads();
        if (tid == 1023) carry += sh[1023];
        __syncthreads();
    }
    if (tid == 0) g_off[0] = 0;
}

// Zero-fill the padding records (<=3 per node). A zero record contributes 0.
__global__ void fillpad_kernel() {
    int i = blockIdx.x * blockDim.x + threadIdx.x;
    if (i >= NN) return;
    int p0 = g_off[i] + g_cnt[i];
    int p1 = g_off[i + 1];
    for (int p = p0; p < p1; p++) {
        float4* dst = (float4*)(g_edge + (size_t)p * ESTRIDE);
        #pragma unroll
        for (int q = 0; q < 8; q++)
            __stcs(dst + q, make_float4(0.f, 0.f, 0.f, 0.f));
    }
}

// ---------------- bucket + per-edge precompute (fused) ---------------------
// Record (floats): [0..19]=sin_t*env/d, [20]=env, [21]=0, [22..23]=pad,
// [24..26]=unit, [27]=j (bit-cast), [28..31]=pad.
__global__ void bucket_pre_kernel(const void* __restrict__ nbrs,
                                  const float* __restrict__ rij) {
    int e = blockIdx.x * blockDim.x + threadIdx.x;
    if (e >= NE) return;
    int i = nb_get(nbrs, 2LL * e);
    int j = nb_get(nbrs, 2LL * e + 1);
    int p = g_off[i] + atomicAdd(&g_cur[i], 1);

    float r0 = rij[3 * (size_t)e];
    float r1 = rij[3 * (size_t)e + 1];
    float r2 = rij[3 * (size_t)e + 2];
    float d2 = r0 * r0 + r1 * r1 + r2 * r2 + 3e-15f;
    float d  = sqrtf(d2);
    float invd = 1.f / d;

    float x = d * PI_OVER_5;
    float s1, c1;
    __sincosf(x, &s1, &c1);
    float env = (d < 5.0f) ? 0.5f * (c1 + 1.f) : 0.f;
    float scale = env * invd;

    float vals[32];
    float sp = 0.f, sc = s1;
    float twoc = 2.f * c1;
    #pragma unroll
    for (int t = 0; t < NRBF; t++) {
        vals[t] = sc * scale;
        float sn = twoc * sc - sp;
        sp = sc; sc = sn;
    }
    vals[20] = env;
    vals[21] = 0.f; vals[22] = 0.f; vals[23] = 0.f;
    vals[24] = r0 * invd;
    vals[25] = r1 * invd;
    vals[26] = r2 * invd;
    vals[27] = __int_as_float(j);
    vals[28] = 0.f; vals[29] = 0.f; vals[30] = 0.f; vals[31] = 0.f;

    float4* dst = (float4*)(g_edge + (size_t)p * ESTRIDE);
    #pragma unroll
    for (int q = 0; q < 8; q++)
        __stcs(dst + q, make_float4(vals[4 * q], vals[4 * q + 1],
                                    vals[4 * q + 2], vals[4 * q + 3]));
}

// ---------------- node MLP + vj repack ------------------------------------
__global__ __launch_bounds__(F) void node_mlp_kernel(
    const float* __restrict__ s,
    const float* __restrict__ vj,
    const float* __restrict__ W1, const float* __restrict__ b1,
    const float* __restrict__ W2, const float* __restrict__ b2)
{
    __shared__ float sh_s[32][F];
    __shared__ float sh_h[32][F];
    const int tid = threadIdx.x;
    const int n0 = blockIdx.x * 32;

    #pragma unroll
    for (int n = 0; n < 32; n++) {
        int node = n0 + n;
        sh_s[n][tid] = (node < NN) ? s[(size_t)node * F + tid] : 0.f;
    }
    __syncthreads();

    const float bb = b1[tid];
    for (int gq = 0; gq < 32; gq += 8) {
        u64 acc2[8];
        #pragma unroll
        for (int n = 0; n < 8; n++) acc2[n] = 0ull;
        for (int k = 0; k < F; k += 2) {
            u64 w2 = pack2(W1[k * F + tid], W1[(k + 1) * F + tid]);
            #pragma unroll
            for (int n = 0; n < 8; n++) {
                u64 s2 = *(const u64*)&sh_s[gq + n][k];
                acc2[n] = fma2(s2, w2, acc2[n]);
            }
        }
        #pragma unroll
        for (int n = 0; n < 8; n++) {
            float lo, hi;
            unpack2(acc2[n], lo, hi);
            float v = lo + hi + bb;
            sh_h[gq + n][tid] = v * (1.f / (1.f + __expf(-v)));
        }
    }
    __syncthreads();

    const float b20 = b2[tid], b21 = b2[tid + F], b22 = b2[tid + 2 * F];
    for (int gq = 0; gq < 32; gq += 8) {
        u64 a0[8], a1[8], a2[8];
        #pragma unroll
        for (int n = 0; n < 8; n++) { a0[n] = 0ull; a1[n] = 0ull; a2[n] = 0ull; }
        for (int k = 0; k < F; k += 2) {
            u64 w20 = pack2(W2[k * C3 + tid],         W2[(k + 1) * C3 + tid]);
            u64 w21 = pack2(W2[k * C3 + F + tid],     W2[(k + 1) * C3 + F + tid]);
            u64 w22 = pack2(W2[k * C3 + 2 * F + tid], W2[(k + 1) * C3 + 2 * F + tid]);
            #pragma unroll
            for (int n = 0; n < 8; n++) {
                u64 h2 = *(const u64*)&sh_h[gq + n][k];
                a0[n] = fma2(h2, w20, a0[n]);
                a1[n] = fma2(h2, w21, a1[n]);
                a2[n] = fma2(h2, w22, a2[n]);
            }
        }
        #pragma unroll
        for (int n = 0; n < 8; n++) {
            int node = n0 + gq + n;
            if (node < NN) {
                float l0, h0, l1, h1, l2, h2v;
                unpack2(a0[n], l0, h0);
                unpack2(a1[n], l1, h1);
                unpack2(a2[n], l2, h2v);
                const float* vp = vj + (size_t)node * C3 + 3 * tid;
                float v0 = vp[0], v1 = vp[1], v2 = vp[2];
                g_phiT[(size_t)node * F + tid] =
                    make_float4(l0 + h0 + b20, l1 + h1 + b21, l2 + h2v + b22, v0);
                g_vhi[(size_t)node * F + tid] = pack2(v1, v2);
            }
        }
    }
}

// ---------------- gather: atomic-free segment sum ---------------------------
__device__ __forceinline__ void gather_body(
    const float* rec,
    const u64* wd0p, const u64* wd1p, const u64* wd2p,
    const float4* __restrict__ phiT, const u64* __restrict__ vhi, int f,
    float& acc_s, float& av0, float& av1, float& av2)
{
    const u64* bp = (const u64*)rec;
    u64 w0p = 0ull, w1p = 0ull, w2p = 0ull;
    #pragma unroll
    for (int t = 0; t < 11; t++) {            // pairs 0..10; pair 10 = (env,0)
        u64 g2 = bp[t];
        w0p = fma2(g2, wd0p[t], w0p);
        w1p = fma2(g2, wd1p[t], w1p);
        w2p = fma2(g2, wd2p[t], w2p);
    }
    float4 uj = *(const float4*)(rec + 24);   // u0,u1,u2,jbits
    const int j = __float_as_int(uj.w);

    float lo, hi;
    unpack2(w0p, lo, hi); float w0 = lo + hi;
    unpack2(w1p, lo, hi); float w1 = lo + hi;
    unpack2(w2p, lo, hi); float w2 = lo + hi;

    float4 ph = phiT[(size_t)j * F + f];      // phi0,phi1,phi2,v0
    float v1, v2;
    unpack2(vhi[(size_t)j * F + f], v1, v2);

    float inv0 = ph.x * w0;
    acc_s     += ph.y * w1;
    float inv2 = ph.z * w2;

    av0 += inv2 * uj.x + inv0 * ph.w;
    av1 += inv2 * uj.y + inv0 * v1;
    av2 += inv2 * uj.z + inv0 * v2;
}

__global__ __launch_bounds__(F, 4) void gather_kernel(
    const float* __restrict__ Wd,
    const float* __restrict__ bd,
    float* __restrict__ out_s,
    float* __restrict__ out_v)
{
    const int i = blockIdx.x;
    const int f = threadIdx.x;

    // 11 packed Wd pairs per channel; pair 10 = (bd, 0) pairs with (env, 0).
    u64 wd0p[11], wd1p[11], wd2p[11];
    #pragma unroll
    for (int t = 0; t < 10; t++) {
        wd0p[t] = pack2(Wd[(2 * t) * C3 + f],         Wd[(2 * t + 1) * C3 + f]);
        wd1p[t] = pack2(Wd[(2 * t) * C3 + F + f],     Wd[(2 * t + 1) * C3 + F + f]);
        wd2p[t] = pack2(Wd[(2 * t) * C3 + 2 * F + f], Wd[(2 * t + 1) * C3 + 2 * F + f]);
    }
    wd0p[10] = pack2(bd[f],         0.f);
    wd1p[10] = pack2(bd[F + f],     0.f);
    wd2p[10] = pack2(bd[2 * F + f], 0.f);

    __shared__ float4 sh4[2][EBATCH * 8];

    float acc_s = 0.f, av0 = 0.f, av1 = 0.f, av2 = 0.f;

    const int e0 = g_off[i];
    const int e1 = g_off[i + 1];
    const float4* src4 = (const float4*)g_edge;
    const float4* phiT = g_phiT;
    const u64*    vhi  = g_vhi;

    // Prologue: load batch 0 into registers.
    int nb = min(EBATCH, e1 - e0);
    float4 s0 = make_float4(0.f, 0.f, 0.f, 0.f), s1 = s0;
    if (f < nb * 8)       s0 = __ldcs(src4 + (size_t)e0 * 8 + f);
    if (f + F < nb * 8)   s1 = __ldcs(src4 + (size_t)e0 * 8 + f + F);

    int buf = 0;
    for (int b = e0; b < e1; b += EBATCH) {
        sh4[buf][f]     = s0;
        sh4[buf][f + F] = s1;

        // Issue next batch's loads before the barrier.
        int bn = b + EBATCH;
        if (bn < e1) {
            int nbn = min(EBATCH, e1 - bn);
            if (f < nbn * 8)     s0 = __ldcs(src4 + (size_t)bn * 8 + f);
            if (f + F < nbn * 8) s1 = __ldcs(src4 + (size_t)bn * 8 + f + F);
        }
        __syncthreads();

        const int nbc = min(EBATCH, e1 - b);   // multiple of 4
        #pragma unroll 4
        for (int k = 0; k < nbc; k++) {
            const float* rec = (const float*)&sh4[buf][k * 8];
            gather_body(rec, wd0p, wd1p, wd2p, phiT, vhi, f,
                        acc_s, av0, av1, av2);
        }
        buf ^= 1;
    }

    __stcs(out_s + (size_t)i * F + f, acc_s);
    float* ov = out_v + (size_t)i * C3 + 3 * f;
    __stcs(ov + 0, av0);
    __stcs(ov + 1, av1);
    __stcs(ov + 2, av2);
}

// ---------------- launch ---------------------------------------------------
extern "C" void kernel_launch(void* const* d_in, const int* in_sizes, int n_in,
                              void* d_out, int out_size) {
    const float* s   = (const float*)d_in[0];
    const float* vj  = (const float*)d_in[1];
    const float* rij = (const float*)d_in[2];
    const void*  nb  = d_in[3];
    const float* W1  = (const float*)d_in[4];
    const float* b1  = (const float*)d_in[5];
    const float* W2  = (const float*)d_in[6];
    const float* b2  = (const float*)d_in[7];
    const float* Wd  = (const float*)d_in[8];
    const float* bd  = (const float*)d_in[9];

    float* out_s = (float*)d_out;
    float* out_v = out_s + (size_t)NN * F;

    detect_kernel<<<1, 256>>>(nb);
    zero_kernel<<<(NN + 255) / 256, 256>>>();
    node_mlp_kernel<<<(NN + 31) / 32, F>>>(s, vj, W1, b1, W2, b2);
    hist_kernel<<<(NE + 255) / 256, 256>>>(nb);
    scan_kernel<<<1, 1024>>>();
    fillpad_kernel<<<(NN + 255) / 256, 256>>>();
    bucket_pre_kernel<<<(NE + 255) / 256, 256>>>(nb, rij);
    gather_kernel<<<NN, F>>>(Wd, bd, out_s, out_v);
}

// round 11
// speedup vs baseline: 1.0960x; 1.0960x over previous
#include <cuda_runtime.h>

#define NN   20000
#define NE   640000
#define F    128
#define NRBF 20
#define C3   384
#define ESTRIDE 32            // floats per edge record (128 B)
#define EBATCH 16
#define PI_OVER_5 0.6283185307179586f

typedef unsigned long long u64;

// ---------------- f32x2 packed-FMA helpers (sm_100+) -----------------------
__device__ __forceinline__ u64 pack2(float lo, float hi) {
    u64 r; asm("mov.b64 %0, {%1, %2};" : "=l"(r) : "f"(lo), "f"(hi)); return r;
}
__device__ __forceinline__ void unpack2(u64 v, float& lo, float& hi) {
    asm("mov.b64 {%0, %1}, %2;" : "=f"(lo), "=f"(hi) : "l"(v));
}
__device__ __forceinline__ u64 fma2(u64 a, u64 b, u64 c) {
    u64 d; asm("fma.rn.f32x2 %0, %1, %2, %3;" : "=l"(d) : "l"(a), "l"(b), "l"(c));
    return d;
}

// ---------------- scratch (__device__ globals; no allocation allowed) ------
__device__ int    g_is64;
__device__ int    g_cnt[NN];
__device__ int    g_cur[NN];
__device__ int    g_off[NN + 1];
__device__ float4 g_phiT[(size_t)NN * F];   // (phi0, phi1, phi2, vj0) per (node,f)
__device__ u64    g_vhi[(size_t)NN * F];    // (vj1, vj2) packed
__device__ float  g_edge[(size_t)NE * ESTRIDE];

// ---------------- index helper: nbrs may be int64 or int32 ----------------
__device__ __forceinline__ int nb_get(const void* nbrs, long long k) {
    if (g_is64) return (int)((const long long*)nbrs)[k];
    return ((const int*)nbrs)[k];
}

__global__ void detect_kernel(const void* nbrs) {
    __shared__ int bad;
    if (threadIdx.x == 0) bad = 0;
    __syncthreads();
    const long long* p = (const long long*)nbrs;
    int mybad = 0;
    for (int e = threadIdx.x; e < 1024; e += 256) {
        long long a = p[2 * e], b = p[2 * e + 1];
        if (a < 0 || a >= NN || b < 0 || b >= NN) mybad = 1;
    }
    if (mybad) atomicOr(&bad, 1);
    __syncthreads();
    if (threadIdx.x == 0) g_is64 = !bad;
}

__global__ void zero_kernel() {
    int i = blockIdx.x * blockDim.x + threadIdx.x;
    if (i < NN) { g_cnt[i] = 0; g_cur[i] = 0; }
}

__global__ void hist_kernel(const void* nbrs) {
    int e = blockIdx.x * blockDim.x + threadIdx.x;
    if (e < NE) {
        int i = nb_get(nbrs, 2LL * e);
        atomicAdd(&g_cnt[i], 1);
    }
}

// Single-block scan over NN counts -> exclusive offsets.
__global__ void scan_kernel() {
    __shared__ int sh[1024];
    __shared__ int carry;
    const int tid = threadIdx.x;
    if (tid == 0) carry = 0;
    __syncthreads();
    for (int base = 0; base < NN; base += 1024) {
        int i = base + tid;
        int v = (i < NN) ? g_cnt[i] : 0;
        sh[tid] = v;
        __syncthreads();
        for (int s = 1; s < 1024; s <<= 1) {
            int t = (tid >= s) ? sh[tid - s] : 0;
            __syncthreads();
            sh[tid] += t;
            __syncthreads();
        }
        if (i < NN) g_off[i + 1] = carry + sh[tid];
        __syncthreads();
        if (tid == 1023) carry += sh[1023];
        __syncthreads();
    }
    if (tid == 0) g_off[0] = 0;
}

// ---------------- bucket + per-edge precompute (fused) ---------------------
// Record (floats): [0..19]=sin_t*env/d, [20]=env, [21..23]=pad,
// [24..26]=unit, [27]=j (bit-cast), [28..31]=pad.
__global__ void bucket_pre_kernel(const void* __restrict__ nbrs,
                                  const float* __restrict__ rij) {
    int e = blockIdx.x * blockDim.x + threadIdx.x;
    if (e >= NE) return;
    int i = nb_get(nbrs, 2LL * e);
    int j = nb_get(nbrs, 2LL * e + 1);
    int p = g_off[i] + atomicAdd(&g_cur[i], 1);

    float r0 = rij[3 * (size_t)e];
    float r1 = rij[3 * (size_t)e + 1];
    float r2 = rij[3 * (size_t)e + 2];
    float d2 = r0 * r0 + r1 * r1 + r2 * r2 + 3e-15f;
    float d  = sqrtf(d2);
    float invd = 1.f / d;

    float x = d * PI_OVER_5;
    float s1, c1;
    __sincosf(x, &s1, &c1);
    float env = (d < 5.0f) ? 0.5f * (c1 + 1.f) : 0.f;
    float scale = env * invd;

    float vals[32];
    float sp = 0.f, sc = s1;
    float twoc = 2.f * c1;
    #pragma unroll
    for (int t = 0; t < NRBF; t++) {
        vals[t] = sc * scale;
        float sn = twoc * sc - sp;
        sp = sc; sc = sn;
    }
    vals[20] = env;
    vals[21] = 0.f; vals[22] = 0.f; vals[23] = 0.f;
    vals[24] = r0 * invd;
    vals[25] = r1 * invd;
    vals[26] = r2 * invd;
    vals[27] = __int_as_float(j);
    vals[28] = 0.f; vals[29] = 0.f; vals[30] = 0.f; vals[31] = 0.f;

    float4* dst = (float4*)(g_edge + (size_t)p * ESTRIDE);
    #pragma unroll
    for (int q = 0; q < 8; q++)
        __stcs(dst + q, make_float4(vals[4 * q], vals[4 * q + 1],
                                    vals[4 * q + 2], vals[4 * q + 3]));
}

// ---------------- node MLP + vj repack ------------------------------------
__global__ __launch_bounds__(F) void node_mlp_kernel(
    const float* __restrict__ s,
    const float* __restrict__ vj,
    const float* __restrict__ W1, const float* __restrict__ b1,
    const float* __restrict__ W2, const float* __restrict__ b2)
{
    __shared__ float sh_s[32][F];
    __shared__ float sh_h[32][F];
    const int tid = threadIdx.x;
    const int n0 = blockIdx.x * 32;

    #pragma unroll
    for (int n = 0; n < 32; n++) {
        int node = n0 + n;
        sh_s[n][tid] = (node < NN) ? s[(size_t)node * F + tid] : 0.f;
    }
    __syncthreads();

    const float bb = b1[tid];
    for (int gq = 0; gq < 32; gq += 8) {
        u64 acc2[8];
        #pragma unroll
        for (int n = 0; n < 8; n++) acc2[n] = 0ull;
        for (int k = 0; k < F; k += 2) {
            u64 w2 = pack2(W1[k * F + tid], W1[(k + 1) * F + tid]);
            #pragma unroll
            for (int n = 0; n < 8; n++) {
                u64 s2 = *(const u64*)&sh_s[gq + n][k];
                acc2[n] = fma2(s2, w2, acc2[n]);
            }
        }
        #pragma unroll
        for (int n = 0; n < 8; n++) {
            float lo, hi;
            unpack2(acc2[n], lo, hi);
            float v = lo + hi + bb;
            sh_h[gq + n][tid] = v * (1.f / (1.f + __expf(-v)));
        }
    }
    __syncthreads();

    const float b20 = b2[tid], b21 = b2[tid + F], b22 = b2[tid + 2 * F];
    for (int gq = 0; gq < 32; gq += 8) {
        u64 a0[8], a1[8], a2[8];
        #pragma unroll
        for (int n = 0; n < 8; n++) { a0[n] = 0ull; a1[n] = 0ull; a2[n] = 0ull; }
        for (int k = 0; k < F; k += 2) {
            u64 w20 = pack2(W2[k * C3 + tid],         W2[(k + 1) * C3 + tid]);
            u64 w21 = pack2(W2[k * C3 + F + tid],     W2[(k + 1) * C3 + F + tid]);
            u64 w22 = pack2(W2[k * C3 + 2 * F + tid], W2[(k + 1) * C3 + 2 * F + tid]);
            #pragma unroll
            for (int n = 0; n < 8; n++) {
                u64 h2 = *(const u64*)&sh_h[gq + n][k];
                a0[n] = fma2(h2, w20, a0[n]);
                a1[n] = fma2(h2, w21, a1[n]);
                a2[n] = fma2(h2, w22, a2[n]);
            }
        }
        #pragma unroll
        for (int n = 0; n < 8; n++) {
            int node = n0 + gq + n;
            if (node < NN) {
                float l0, h0, l1, h1, l2, h2v;
                unpack2(a0[n], l0, h0);
                unpack2(a1[n], l1, h1);
                unpack2(a2[n], l2, h2v);
                const float* vp = vj + (size_t)node * C3 + 3 * tid;
                float v0 = vp[0], v1 = vp[1], v2 = vp[2];
                g_phiT[(size_t)node * F + tid] =
                    make_float4(l0 + h0 + b20, l1 + h1 + b21, l2 + h2v + b22, v0);
                g_vhi[(size_t)node * F + tid] = pack2(v1, v2);
            }
        }
    }
}

// ---------------- gather: atomic-free segment sum ---------------------------
__device__ __forceinline__ void gather_body(
    const float* rec,
    const u64* wd0p, const u64* wd1p, const u64* wd2p,
    float wde0, float wde1, float wde2,
    const float4* __restrict__ phiT, const u64* __restrict__ vhi, int f,
    float& acc_s, float& av0, float& av1, float& av2)
{
    const u64* bp = (const u64*)rec;
    u64 w0p = 0ull, w1p = 0ull, w2p = 0ull;
    #pragma unroll
    for (int t = 0; t < NRBF / 2; t++) {
        u64 g2 = bp[t];
        w0p = fma2(g2, wd0p[t], w0p);
        w1p = fma2(g2, wd1p[t], w1p);
        w2p = fma2(g2, wd2p[t], w2p);
    }
    const float env = rec[20];
    float4 uj = *(const float4*)(rec + 24);   // u0,u1,u2,jbits
    const int j = __float_as_int(uj.w);

    float lo, hi;
    unpack2(w0p, lo, hi); float w0 = fmaf(env, wde0, lo + hi);
    unpack2(w1p, lo, hi); float w1 = fmaf(env, wde1, lo + hi);
    unpack2(w2p, lo, hi); float w2 = fmaf(env, wde2, lo + hi);

    float4 ph = phiT[(size_t)j * F + f];      // phi0,phi1,phi2,v0
    float v1, v2;
    unpack2(vhi[(size_t)j * F + f], v1, v2);

    float inv0 = ph.x * w0;
    acc_s     += ph.y * w1;
    float inv2 = ph.z * w2;

    av0 += inv2 * uj.x + inv0 * ph.w;
    av1 += inv2 * uj.y + inv0 * v1;
    av2 += inv2 * uj.z + inv0 * v2;
}

__global__ __launch_bounds__(F, 4) void gather_kernel(
    const float* __restrict__ Wd,
    const float* __restrict__ bd,
    float* __restrict__ out_s,
    float* __restrict__ out_v)
{
    const int i = blockIdx.x;
    const int f = threadIdx.x;

    u64 wd0p[NRBF / 2], wd1p[NRBF / 2], wd2p[NRBF / 2];
    #pragma unroll
    for (int t = 0; t < NRBF / 2; t++) {
        wd0p[t] = pack2(Wd[(2 * t) * C3 + f],         Wd[(2 * t + 1) * C3 + f]);
        wd1p[t] = pack2(Wd[(2 * t) * C3 + F + f],     Wd[(2 * t + 1) * C3 + F + f]);
        wd2p[t] = pack2(Wd[(2 * t) * C3 + 2 * F + f], Wd[(2 * t + 1) * C3 + 2 * F + f]);
    }
    const float wde0 = bd[f], wde1 = bd[F + f], wde2 = bd[2 * F + f];

    __shared__ float4 sh4[EBATCH * 8];

    float acc_s = 0.f, av0 = 0.f, av1 = 0.f, av2 = 0.f;

    const int e0 = g_off[i];
    const int e1 = g_off[i + 1];
    const float4* src4 = (const float4*)g_edge;
    const float4* phiT = g_phiT;
    const u64*    vhi  = g_vhi;

    for (int b = e0; b < e1; b += EBATCH) {
        const int nb = min(EBATCH, e1 - b);
        __syncthreads();
        if (f < nb * 8) sh4[f] = __ldcs(src4 + (size_t)b * 8 + f);
        __syncthreads();

        if (nb == EBATCH) {
            #pragma unroll 4
            for (int k = 0; k < EBATCH; k++) {
                const float* rec = (const float*)&sh4[k * 8];
                gather_body(rec, wd0p, wd1p, wd2p, wde0, wde1, wde2,
                            phiT, vhi, f, acc_s, av0, av1, av2);
            }
        } else {
            for (int k = 0; k < nb; k++) {
                const float* rec = (const float*)&sh4[k * 8];
                gather_body(rec, wd0p, wd1p, wd2p, wde0, wde1, wde2,
                            phiT, vhi, f, acc_s, av0, av1, av2);
            }
        }
    }

    __stcs(out_s + (size_t)i * F + f, acc_s);
    float* ov = out_v + (size_t)i * C3 + 3 * f;
    __stcs(ov + 0, av0);
    __stcs(ov + 1, av1);
    __stcs(ov + 2, av2);
}

// ---------------- launch ---------------------------------------------------
extern "C" void kernel_launch(void* const* d_in, const int* in_sizes, int n_in,
                              void* d_out, int out_size) {
    const float* s   = (const float*)d_in[0];
    const float* vj  = (const float*)d_in[1];
    const float* rij = (const float*)d_in[2];
    const void*  nb  = d_in[3];
    const float* W1  = (const float*)d_in[4];
    const float* b1  = (const float*)d_in[5];
    const float* W2  = (const float*)d_in[6];
    const float* b2  = (const float*)d_in[7];
    const float* Wd  = (const float*)d_in[8];
    const float* bd  = (const float*)d_in[9];

    float* out_s = (float*)d_out;
    float* out_v = out_s + (size_t)NN * F;

    detect_kernel<<<1, 256>>>(nb);
    zero_kernel<<<(NN + 255) / 256, 256>>>();
    node_mlp_kernel<<<(NN + 31) / 32, F>>>(s, vj, W1, b1, W2, b2);
    hist_kernel<<<(NE + 255) / 256, 256>>>(nb);
    scan_kernel<<<1, 1024>>>();
    bucket_pre_kernel<<<(NE + 255) / 256, 256>>>(nb, rij);
    gather_kernel<<<NN, F>>>(Wd, bd, out_s, out_v);
}

// round 12
// speedup vs baseline: 1.1049x; 1.0081x over previous
#include <cuda_runtime.h>

#define NN   20000
#define NE   640000
#define F    128
#define NRBF 20
#define C3   384
#define ESTRIDE 32            // floats per edge record (128 B)
#define EBATCH 16
#define PI_OVER_5 0.6283185307179586f

typedef unsigned long long u64;

// ---------------- f32x2 packed-FMA helpers (sm_100+) -----------------------
__device__ __forceinline__ u64 pack2(float lo, float hi) {
    u64 r; asm("mov.b64 %0, {%1, %2};" : "=l"(r) : "f"(lo), "f"(hi)); return r;
}
__device__ __forceinline__ void unpack2(u64 v, float& lo, float& hi) {
    asm("mov.b64 {%0, %1}, %2;" : "=f"(lo), "=f"(hi) : "l"(v));
}
__device__ __forceinline__ u64 fma2(u64 a, u64 b, u64 c) {
    u64 d; asm("fma.rn.f32x2 %0, %1, %2, %3;" : "=l"(d) : "l"(a), "l"(b), "l"(c));
    return d;
}

// ---------------- cp.async helpers -----------------------------------------
__device__ __forceinline__ void cp_async16(void* smem, const void* gmem) {
    unsigned sa = (unsigned)__cvta_generic_to_shared(smem);
    asm volatile("cp.async.cg.shared.global [%0], [%1], 16;"
                 :: "r"(sa), "l"(gmem) : "memory");
}
__device__ __forceinline__ void cp_async_commit() {
    asm volatile("cp.async.commit_group;" ::: "memory");
}
__device__ __forceinline__ void cp_async_wait1() {
    asm volatile("cp.async.wait_group 1;" ::: "memory");
}

// ---------------- scratch (__device__ globals; no allocation allowed) ------
__device__ int    g_is64;
__device__ int    g_cnt[NN];
__device__ int    g_cur[NN];
__device__ int    g_off[NN + 1];
__device__ float4 g_phiT[(size_t)NN * F];     // (phi0, phi1, phi2, pad) per (node,f)
__device__ float  g_edge[(size_t)NE * ESTRIDE];

// ---------------- index helper: nbrs may be int64 or int32 ----------------
__device__ __forceinline__ int nb_get(const void* nbrs, long long k) {
    if (g_is64) return (int)((const long long*)nbrs)[k];
    return ((const int*)nbrs)[k];
}

__global__ void detect_kernel(const void* nbrs) {
    __shared__ int bad;
    if (threadIdx.x == 0) bad = 0;
    __syncthreads();
    const long long* p = (const long long*)nbrs;
    int mybad = 0;
    for (int e = threadIdx.x; e < 1024; e += 256) {
        long long a = p[2 * e], b = p[2 * e + 1];
        if (a < 0 || a >= NN || b < 0 || b >= NN) mybad = 1;
    }
    if (mybad) atomicOr(&bad, 1);
    __syncthreads();
    if (threadIdx.x == 0) g_is64 = !bad;
}

__global__ void zero_kernel() {
    int i = blockIdx.x * blockDim.x + threadIdx.x;
    if (i < NN) { g_cnt[i] = 0; g_cur[i] = 0; }
}

__global__ void hist_kernel(const void* nbrs) {
    int e = blockIdx.x * blockDim.x + threadIdx.x;
    if (e < NE) {
        int i = nb_get(nbrs, 2LL * e);
        atomicAdd(&g_cnt[i], 1);
    }
}

// Single-block scan over NN counts -> exclusive offsets.
__global__ void scan_kernel() {
    __shared__ int sh[1024];
    __shared__ int carry;
    const int tid = threadIdx.x;
    if (tid == 0) carry = 0;
    __syncthreads();
    for (int base = 0; base < NN; base += 1024) {
        int i = base + tid;
        int v = (i < NN) ? g_cnt[i] : 0;
        sh[tid] = v;
        __syncthreads();
        for (int s = 1; s < 1024; s <<= 1) {
            int t = (tid >= s) ? sh[tid - s] : 0;
            __syncthreads();
            sh[tid] += t;
            __syncthreads();
        }
        if (i < NN) g_off[i + 1] = carry + sh[tid];
        __syncthreads();
        if (tid == 1023) carry += sh[1023];
        __syncthreads();
    }
    if (tid == 0) g_off[0] = 0;
}

// ---------------- bucket + per-edge precompute (fused) ---------------------
// Record (floats): [0..19]=sin_t*env/d, [20]=env, [21..23]=pad,
// [24..26]=unit, [27]=j (bit-cast), [28..31]=pad.
__global__ void bucket_pre_kernel(const void* __restrict__ nbrs,
                                  const float* __restrict__ rij) {
    int e = blockIdx.x * blockDim.x + threadIdx.x;
    if (e >= NE) return;
    int i = nb_get(nbrs, 2LL * e);
    int j = nb_get(nbrs, 2LL * e + 1);
    int p = g_off[i] + atomicAdd(&g_cur[i], 1);

    float r0 = rij[3 * (size_t)e];
    float r1 = rij[3 * (size_t)e + 1];
    float r2 = rij[3 * (size_t)e + 2];
    float d2 = r0 * r0 + r1 * r1 + r2 * r2 + 3e-15f;
    float d  = sqrtf(d2);
    float invd = 1.f / d;

    float x = d * PI_OVER_5;
    float s1, c1;
    __sincosf(x, &s1, &c1);
    float env = (d < 5.0f) ? 0.5f * (c1 + 1.f) : 0.f;
    float scale = env * invd;

    float vals[32];
    float sp = 0.f, sc = s1;
    float twoc = 2.f * c1;
    #pragma unroll
    for (int t = 0; t < NRBF; t++) {
        vals[t] = sc * scale;
        float sn = twoc * sc - sp;
        sp = sc; sc = sn;
    }
    vals[20] = env;
    vals[21] = 0.f; vals[22] = 0.f; vals[23] = 0.f;
    vals[24] = r0 * invd;
    vals[25] = r1 * invd;
    vals[26] = r2 * invd;
    vals[27] = __int_as_float(j);
    vals[28] = 0.f; vals[29] = 0.f; vals[30] = 0.f; vals[31] = 0.f;

    float4* dst = (float4*)(g_edge + (size_t)p * ESTRIDE);
    #pragma unroll
    for (int q = 0; q < 8; q++)
        __stcs(dst + q, make_float4(vals[4 * q], vals[4 * q + 1],
                                    vals[4 * q + 2], vals[4 * q + 3]));
}

// ---------------- node MLP: phiT = silu(s@W1+b1)@W2 + b2 (f32x2) ----------
__global__ __launch_bounds__(F) void node_mlp_kernel(
    const float* __restrict__ s,
    const float* __restrict__ W1, const float* __restrict__ b1,
    const float* __restrict__ W2, const float* __restrict__ b2)
{
    __shared__ float sh_s[32][F];
    __shared__ float sh_h[32][F];
    const int tid = threadIdx.x;
    const int n0 = blockIdx.x * 32;

    #pragma unroll
    for (int n = 0; n < 32; n++) {
        int node = n0 + n;
        sh_s[n][tid] = (node < NN) ? s[(size_t)node * F + tid] : 0.f;
    }
    __syncthreads();

    const float bb = b1[tid];
    for (int gq = 0; gq < 32; gq += 8) {
        u64 acc2[8];
        #pragma unroll
        for (int n = 0; n < 8; n++) acc2[n] = 0ull;
        for (int k = 0; k < F; k += 2) {
            u64 w2 = pack2(W1[k * F + tid], W1[(k + 1) * F + tid]);
            #pragma unroll
            for (int n = 0; n < 8; n++) {
                u64 s2 = *(const u64*)&sh_s[gq + n][k];
                acc2[n] = fma2(s2, w2, acc2[n]);
            }
        }
        #pragma unroll
        for (int n = 0; n < 8; n++) {
            float lo, hi;
            unpack2(acc2[n], lo, hi);
            float v = lo + hi + bb;
            sh_h[gq + n][tid] = v * (1.f / (1.f + __expf(-v)));
        }
    }
    __syncthreads();

    const float b20 = b2[tid], b21 = b2[tid + F], b22 = b2[tid + 2 * F];
    for (int gq = 0; gq < 32; gq += 8) {
        u64 a0[8], a1[8], a2[8];
        #pragma unroll
        for (int n = 0; n < 8; n++) { a0[n] = 0ull; a1[n] = 0ull; a2[n] = 0ull; }
        for (int k = 0; k < F; k += 2) {
            u64 w20 = pack2(W2[k * C3 + tid],         W2[(k + 1) * C3 + tid]);
            u64 w21 = pack2(W2[k * C3 + F + tid],     W2[(k + 1) * C3 + F + tid]);
            u64 w22 = pack2(W2[k * C3 + 2 * F + tid], W2[(k + 1) * C3 + 2 * F + tid]);
            #pragma unroll
            for (int n = 0; n < 8; n++) {
                u64 h2 = *(const u64*)&sh_h[gq + n][k];
                a0[n] = fma2(h2, w20, a0[n]);
                a1[n] = fma2(h2, w21, a1[n]);
                a2[n] = fma2(h2, w22, a2[n]);
            }
        }
        #pragma unroll
        for (int n = 0; n < 8; n++) {
            int node = n0 + gq + n;
            if (node < NN) {
                float l0, h0, l1, h1, l2, h2v;
                unpack2(a0[n], l0, h0);
                unpack2(a1[n], l1, h1);
                unpack2(a2[n], l2, h2v);
                g_phiT[(size_t)node * F + tid] =
                    make_float4(l0 + h0 + b20, l1 + h1 + b21, l2 + h2v + b22, 0.f);
            }
        }
    }
}

// ---------------- gather: atomic-free segment sum ---------------------------
__device__ __forceinline__ void gather_body(
    const float* rec,
    const u64* wd0p, const u64* wd1p, const u64* wd2p,
    float wde0, float wde1, float wde2,
    const float* __restrict__ vj, const float4* __restrict__ phiT, int f,
    float& acc_s, float& av0, float& av1, float& av2)
{
    const u64* bp = (const u64*)rec;
    u64 w0p = 0ull, w1p = 0ull, w2p = 0ull;
    #pragma unroll
    for (int t = 0; t < NRBF / 2; t++) {
        u64 g2 = bp[t];
        w0p = fma2(g2, wd0p[t], w0p);
        w1p = fma2(g2, wd1p[t], w1p);
        w2p = fma2(g2, wd2p[t], w2p);
    }
    const float env = rec[20];
    float4 uj = *(const float4*)(rec + 24);   // u0,u1,u2,jbits
    const int j = __float_as_int(uj.w);

    float lo, hi;
    unpack2(w0p, lo, hi); float w0 = fmaf(env, wde0, lo + hi);
    unpack2(w1p, lo, hi); float w1 = fmaf(env, wde1, lo + hi);
    unpack2(w2p, lo, hi); float w2 = fmaf(env, wde2, lo + hi);

    float4 ph = phiT[(size_t)j * F + f];
    const float* vp = vj + (size_t)j * C3 + 3 * f;
    float va = vp[0], vb = vp[1], vc = vp[2];

    float inv0 = ph.x * w0;
    acc_s     += ph.y * w1;
    float inv2 = ph.z * w2;

    av0 += inv2 * uj.x + inv0 * va;
    av1 += inv2 * uj.y + inv0 * vb;
    av2 += inv2 * uj.z + inv0 * vc;
}

__global__ __launch_bounds__(F, 4) void gather_kernel(
    const float* __restrict__ vj,
    const float* __restrict__ Wd,
    const float* __restrict__ bd,
    float* __restrict__ out_s,
    float* __restrict__ out_v)
{
    const int i = blockIdx.x;
    const int f = threadIdx.x;

    u64 wd0p[NRBF / 2], wd1p[NRBF / 2], wd2p[NRBF / 2];
    #pragma unroll
    for (int t = 0; t < NRBF / 2; t++) {
        wd0p[t] = pack2(Wd[(2 * t) * C3 + f],         Wd[(2 * t + 1) * C3 + f]);
        wd1p[t] = pack2(Wd[(2 * t) * C3 + F + f],     Wd[(2 * t + 1) * C3 + F + f]);
        wd2p[t] = pack2(Wd[(2 * t) * C3 + 2 * F + f], Wd[(2 * t + 1) * C3 + 2 * F + f]);
    }
    const float wde0 = bd[f], wde1 = bd[F + f], wde2 = bd[2 * F + f];

    __shared__ float4 sh4[2][EBATCH * 8];

    float acc_s = 0.f, av0 = 0.f, av1 = 0.f, av2 = 0.f;

    const int e0 = g_off[i];
    const int e1 = g_off[i + 1];
    const float4* src4 = (const float4*)g_edge;
    const float4* phiT = g_phiT;

    // Prologue: async-copy batch 0 into buffer 0.
    {
        int nb0 = min(EBATCH, e1 - e0);
        if (f < nb0 * 8)
            cp_async16(&sh4[0][f], src4 + (size_t)e0 * 8 + f);
        cp_async_commit();
    }

    int buf = 0;
    for (int b = e0; b < e1; b += EBATCH) {
        // Issue next batch's copy into the other buffer, then wait for current.
        int bn = b + EBATCH;
        if (bn < e1) {
            int nbn = min(EBATCH, e1 - bn);
            if (f < nbn * 8)
                cp_async16(&sh4[buf ^ 1][f], src4 + (size_t)bn * 8 + f);
        }
        cp_async_commit();
        cp_async_wait1();          // current batch's group complete
        __syncthreads();           // make copies visible block-wide

        const int nb = min(EBATCH, e1 - b);
        if (nb == EBATCH) {
            #pragma unroll 4
            for (int k = 0; k < EBATCH; k++) {
                const float* rec = (const float*)&sh4[buf][k * 8];
                gather_body(rec, wd0p, wd1p, wd2p, wde0, wde1, wde2,
                            vj, phiT, f, acc_s, av0, av1, av2);
            }
        } else {
            for (int k = 0; k < nb; k++) {
                const float* rec = (const float*)&sh4[buf][k * 8];
                gather_body(rec, wd0p, wd1p, wd2p, wde0, wde1, wde2,
                            vj, phiT, f, acc_s, av0, av1, av2);
            }
        }
        __syncthreads();           // compute done before this buffer is refilled
        buf ^= 1;
    }

    __stcs(out_s + (size_t)i * F + f, acc_s);
    float* ov = out_v + (size_t)i * C3 + 3 * f;
    __stcs(ov + 0, av0);
    __stcs(ov + 1, av1);
    __stcs(ov + 2, av2);
}

// ---------------- launch ---------------------------------------------------
extern "C" void kernel_launch(void* const* d_in, const int* in_sizes, int n_in,
                              void* d_out, int out_size) {
    const float* s   = (const float*)d_in[0];
    const float* vj  = (const float*)d_in[1];
    const float* rij = (const float*)d_in[2];
    const void*  nb  = d_in[3];
    const float* W1  = (const float*)d_in[4];
    const float* b1  = (const float*)d_in[5];
    const float* W2  = (const float*)d_in[6];
    const float* b2  = (const float*)d_in[7];
    const float* Wd  = (const float*)d_in[8];
    const float* bd  = (const float*)d_in[9];

    float* out_s = (float*)d_out;
    float* out_v = out_s + (size_t)NN * F;

    detect_kernel<<<1, 256>>>(nb);
    zero_kernel<<<(NN + 255) / 256, 256>>>();
    node_mlp_kernel<<<(NN + 31) / 32, F>>>(s, W1, b1, W2, b2);
    hist_kernel<<<(NE + 255) / 256, 256>>>(nb);
    scan_kernel<<<1, 1024>>>();
    bucket_pre_kernel<<<(NE + 255) / 256, 256>>>(nb, rij);
    gather_kernel<<<NN, F>>>(vj, Wd, bd, out_s, out_v);
}